// round 16
// baseline (speedup 1.0000x reference)
#include <cuda_runtime.h>
#include <math.h>

#define BB 4
#define NN 16384
#define CC 128
#define MM 128
#define NS 512
#define ROW (3 + CC)        // 131 floats per pooled row
#define NBOX (BB * MM)      // 512
#define BLOCK 256
#define NWARP (BLOCK / 32)
#define WORDS (NN / 32)     // 512 mask words per box
#define ASPLIT 8            // box-loop split in kA
#define BOXCHUNK (MM / ASPLIT)   // 16 boxes per kA CTA
#define PCHUNK 1024         // points per kA CTA (4 per thread)
#define PCHUNKS (NN / PCHUNK)    // 16
#define GPARTS 4            // gather CTAs per box
#define GROWS (NS / GPARTS) // 128 rows per gather CTA
#define PARTF (GROWS * ROW) // 16768 floats per part

__device__ unsigned g_mask[NBOX * WORDS];   // inside-mask bitmap [box][word]
__device__ int g_rows[NBOX * NS];           // wrapped source row per output slot
__device__ int g_cnt[NBOX];

// ---------------- Kernel A: mask (point-resident, 4 points/thread) ----------------
// grid = BB(4) * PCHUNKS(16) * ASPLIT(8) = 512  -> single wave
// point for group g: pc*1024 + w*128 + g*32 + lane  => mask word = pc*32 + w*4 + g
__global__ __launch_bounds__(BLOCK)
void kA_mask(const float* __restrict__ points,   // [B,N,3]
             const float* __restrict__ boxes)    // [B,M,7]
{
    const int bs   = blockIdx.x;
    const int sb   = bs & (ASPLIT - 1);
    const int pc   = (bs >> 3) & (PCHUNKS - 1);
    const int b    = bs >> 7;
    const int tid  = threadIdx.x;
    const int w    = tid >> 5;
    const int lane = tid & 31;
    const int box0 = sb * BOXCHUNK;

    __shared__ float4 s_prm[BOXCHUNK * 2];        // {cx,cy,cz,hx},{hy,hz,ch,sh}

    if (tid < BOXCHUNK) {
        const float* bx = boxes + (size_t)(b * MM + box0 + tid) * 7;
        const float hx = __fmul_rn(__fadd_rn(bx[3], 2.0f), 0.5f);
        const float hy = __fmul_rn(__fadd_rn(bx[4], 2.0f), 0.5f);
        const float hz = __fmul_rn(__fadd_rn(bx[5], 2.0f), 0.5f);
        const double hd = (double)bx[6];
        s_prm[tid * 2 + 0] = make_float4(bx[0], bx[1], bx[2], hx);
        s_prm[tid * 2 + 1] = make_float4(hy, hz, (float)cos(hd), (float)sin(hd));
    }

    float px[4], py[4], pz[4];
    const int i0 = pc * PCHUNK + w * 128 + lane;
    #pragma unroll
    for (int g = 0; g < 4; ++g) {
        const float* p = points + ((size_t)b * NN + i0 + g * 32) * 3;
        px[g] = p[0]; py[g] = p[1]; pz[g] = p[2];
    }
    __syncthreads();

    // contiguous 4 words per (warp, box): base word = pc*32 + w*4
    uint4* gm4 = (uint4*)(g_mask + (size_t)(b * MM + box0) * WORDS + pc * 32 + w * 4);

    #pragma unroll 8
    for (int bi = 0; bi < BOXCHUNK; ++bi) {
        const float4 A  = s_prm[bi * 2 + 0];
        const float4 Bp = s_prm[bi * 2 + 1];
        unsigned ball[4];
        #pragma unroll
        for (int g = 0; g < 4; ++g) {
            const float sx = px[g] - A.x;
            const float sy = py[g] - A.y;
            const float sz = pz[g] - A.z;
            const float lx = __fadd_rn(__fmul_rn(sx, Bp.z), __fmul_rn(sy, Bp.w));
            const float ly = __fadd_rn(__fmul_rn(-sx, Bp.w), __fmul_rn(sy, Bp.z));
            const bool pred = (fabsf(lx) < A.w) & (fabsf(ly) < Bp.x) & (fabsf(sz) < Bp.y);
            ball[g] = __ballot_sync(0xffffffffu, pred);
        }
        if (lane == 0)
            gm4[(size_t)bi * (WORDS / 4)] = make_uint4(ball[0], ball[1], ball[2], ball[3]);
    }
}

// ---------------- Kernel B: scan masks -> wrapped row indices (1 CTA/box) ----------------
__global__ __launch_bounds__(BLOCK)
void kB_scan(float* __restrict__ out)
{
    const int bm = blockIdx.x;
    const int tid  = threadIdx.x;
    const int w    = tid >> 5;
    const int lane = tid & 31;

    __shared__ int s_idx[NS];
    __shared__ int s_wtot[NWARP];
    __shared__ int s_cnt;

    const unsigned* gm = g_mask + (size_t)bm * WORDS;
    const unsigned w0 = gm[tid * 2 + 0];
    const unsigned w1 = gm[tid * 2 + 1];
    const int c0 = __popc(w0);
    const int myc = c0 + __popc(w1);

    int scan = myc;
    #pragma unroll
    for (int d = 1; d < 32; d <<= 1) {
        const int v = __shfl_up_sync(0xffffffffu, scan, d);
        if (lane >= d) scan += v;
    }
    if (lane == 31) s_wtot[w] = scan;
    __syncthreads();
    int wbase = 0, tot = 0;
    #pragma unroll
    for (int j = 0; j < NWARP; ++j) {
        const int c = s_wtot[j];
        if (j < w) wbase += c;
        tot += c;
    }
    const int excl = wbase + scan - myc;

    if (excl < NS && myc) {
        int p = excl;
        unsigned ww = w0;
        while (ww) {
            const int bit = __ffs(ww) - 1;
            ww &= ww - 1;
            if (p < NS) s_idx[p] = tid * 64 + bit;
            ++p;
        }
        p = excl + c0;
        ww = w1;
        while (ww) {
            const int bit = __ffs(ww) - 1;
            ww &= ww - 1;
            if (p < NS) s_idx[p] = tid * 64 + 32 + bit;
            ++p;
        }
    }
    if (tid == 0) s_cnt = tot;
    __syncthreads();

    const int cnt = s_cnt;
    const size_t flag_base = (size_t)NBOX * NS * ROW;
    if (tid == 0) {
        g_cnt[bm] = cnt;
        __stcs(out + flag_base + bm, (cnt == 0) ? 1.0f : 0.0f);
    }
    if (cnt == 0) return;
    for (int k = tid; k < NS; k += BLOCK)
        g_rows[bm * NS + k] = s_idx[(cnt >= NS) ? k : (k % cnt)];
}

// ---------------- Kernel C: pure gather (4 CTAs/box, 4 rows/warp one-shot, streaming stores) ----------------
__global__ __launch_bounds__(BLOCK)
void kC_gather(const float* __restrict__ points,
               const float* __restrict__ feats,
               float* __restrict__ out)
{
    const int part = blockIdx.x & (GPARTS - 1);
    const int bm   = blockIdx.x >> 2;
    const int b    = bm >> 7;
    const int k0   = part * GROWS;
    const int tid  = threadIdx.x;
    const int w    = tid >> 5;
    const int lane = tid & 31;

    const int cnt = g_cnt[bm];
    const size_t obase = (size_t)bm * NS * ROW + (size_t)k0 * ROW;

    if (cnt == 0) {
        float4* o4 = (float4*)(out + obase);
        const float4 z = make_float4(0.f, 0.f, 0.f, 0.f);
        for (int e = tid; e < PARTF / 4; e += BLOCK)
            __stcs(o4 + e, z);
        return;
    }

    __shared__ int s_row[GROWS];
    if (tid < GROWS) s_row[tid] = __ldg(&g_rows[bm * NS + k0 + tid]);
    __syncthreads();

    const float* pts = points + (size_t)b * NN * 3;
    const float* ft  = feats  + (size_t)b * NN * CC;

    // 4 batches of 4 rows per warp; per batch all 20 LDGs issued before stores.
    #pragma unroll
    for (int it = 0; it < GROWS / (4 * NWARP); ++it) {
        const int r0 = 4 * (w + NWARP * it);
        int idx[4];
        #pragma unroll
        for (int i = 0; i < 4; ++i) idx[i] = s_row[r0 + i];

        float v[4][4];
        #pragma unroll
        for (int i = 0; i < 4; ++i) {
            const float* src = ft + (size_t)idx[i] * CC;
            #pragma unroll
            for (int j = 0; j < 4; ++j) v[i][j] = src[lane + 32 * j];
        }
        float pv[4];
        #pragma unroll
        for (int i = 0; i < 4; ++i)
            pv[i] = (lane < 3) ? pts[idx[i] * 3 + lane] : 0.f;

        #pragma unroll
        for (int i = 0; i < 4; ++i) {
            const size_t base = obase + (size_t)(r0 + i) * ROW;
            if (lane < 3) __stcs(out + base + lane, pv[i]);
            float* dst = out + base + 3;
            #pragma unroll
            for (int j = 0; j < 4; ++j) __stcs(dst + lane + 32 * j, v[i][j]);
        }
    }
}

extern "C" void kernel_launch(void* const* d_in, const int* in_sizes, int n_in,
                              void* d_out, int out_size) {
    const float* points = (const float*)d_in[0];   // [4,16384,3]
    const float* feats  = (const float*)d_in[1];   // [4,16384,128]
    const float* boxes  = (const float*)d_in[2];   // [4,128,7]
    float* out = (float*)d_out;
    kA_mask<<<BB * PCHUNKS * ASPLIT, BLOCK>>>(points, boxes);
    kB_scan<<<NBOX, BLOCK>>>(out);
    kC_gather<<<NBOX * GPARTS, BLOCK>>>(points, feats, out);
}

// round 17
// speedup vs baseline: 1.0775x; 1.0775x over previous
#include <cuda_runtime.h>
#include <math.h>

#define BB 4
#define NN 16384
#define CC 128
#define MM 128
#define NS 512
#define ROW (3 + CC)        // 131 floats per pooled row
#define NBOX (BB * MM)      // 512
#define BLOCK 256
#define NWARP (BLOCK / 32)
#define WORDS (NN / 32)     // 512 mask words per box
#define ASPLIT 8            // box-loop split in kA
#define BOXCHUNK (MM / ASPLIT)   // 16 boxes per kA CTA
#define PCHUNK 1024         // points per kA CTA (4 per thread)
#define PCHUNKS (NN / PCHUNK)    // 16
#define GPARTS 8            // gather CTAs per box
#define GROWS (NS / GPARTS) // 64 rows per gather CTA
#define PARTF (GROWS * ROW) // 8384 floats per part

__device__ unsigned g_mask[NBOX * WORDS];   // inside-mask bitmap [box][word]
__device__ int g_rows[NBOX * NS];           // wrapped source row per output slot
__device__ int g_cnt[NBOX];

// ---------------- Kernel A: mask (point-resident, 4 points/thread) ----------------
// grid = BB(4) * PCHUNKS(16) * ASPLIT(8) = 512  -> single wave
// point for group g: pc*1024 + w*128 + g*32 + lane  => mask word = pc*32 + w*4 + g
__global__ __launch_bounds__(BLOCK)
void kA_mask(const float* __restrict__ points,   // [B,N,3]
             const float* __restrict__ boxes)    // [B,M,7]
{
    const int bs   = blockIdx.x;
    const int sb   = bs & (ASPLIT - 1);
    const int pc   = (bs >> 3) & (PCHUNKS - 1);
    const int b    = bs >> 7;
    const int tid  = threadIdx.x;
    const int w    = tid >> 5;
    const int lane = tid & 31;
    const int box0 = sb * BOXCHUNK;

    __shared__ float4 s_prm[BOXCHUNK * 2];        // {cx,cy,cz,hx},{hy,hz,ch,sh}

    if (tid < BOXCHUNK) {
        const float* bx = boxes + (size_t)(b * MM + box0 + tid) * 7;
        const float hx = __fmul_rn(__fadd_rn(bx[3], 2.0f), 0.5f);
        const float hy = __fmul_rn(__fadd_rn(bx[4], 2.0f), 0.5f);
        const float hz = __fmul_rn(__fadd_rn(bx[5], 2.0f), 0.5f);
        const double hd = (double)bx[6];
        s_prm[tid * 2 + 0] = make_float4(bx[0], bx[1], bx[2], hx);
        s_prm[tid * 2 + 1] = make_float4(hy, hz, (float)cos(hd), (float)sin(hd));
    }

    float px[4], py[4], pz[4];
    const int i0 = pc * PCHUNK + w * 128 + lane;
    #pragma unroll
    for (int g = 0; g < 4; ++g) {
        const float* p = points + ((size_t)b * NN + i0 + g * 32) * 3;
        px[g] = p[0]; py[g] = p[1]; pz[g] = p[2];
    }
    __syncthreads();

    // contiguous 4 words per (warp, box): base word = pc*32 + w*4
    uint4* gm4 = (uint4*)(g_mask + (size_t)(b * MM + box0) * WORDS + pc * 32 + w * 4);

    #pragma unroll 8
    for (int bi = 0; bi < BOXCHUNK; ++bi) {
        const float4 A  = s_prm[bi * 2 + 0];
        const float4 Bp = s_prm[bi * 2 + 1];
        unsigned ball[4];
        #pragma unroll
        for (int g = 0; g < 4; ++g) {
            const float sx = px[g] - A.x;
            const float sy = py[g] - A.y;
            const float sz = pz[g] - A.z;
            const float lx = __fadd_rn(__fmul_rn(sx, Bp.z), __fmul_rn(sy, Bp.w));
            const float ly = __fadd_rn(__fmul_rn(-sx, Bp.w), __fmul_rn(sy, Bp.z));
            const bool pred = (fabsf(lx) < A.w) & (fabsf(ly) < Bp.x) & (fabsf(sz) < Bp.y);
            ball[g] = __ballot_sync(0xffffffffu, pred);
        }
        if (lane == 0)
            gm4[(size_t)bi * (WORDS / 4)] = make_uint4(ball[0], ball[1], ball[2], ball[3]);
    }
}

// ---------------- Kernel B: scan masks -> wrapped row indices (1 CTA/box) ----------------
__global__ __launch_bounds__(BLOCK)
void kB_scan(float* __restrict__ out)
{
    const int bm = blockIdx.x;
    const int tid  = threadIdx.x;
    const int w    = tid >> 5;
    const int lane = tid & 31;

    __shared__ int s_idx[NS];
    __shared__ int s_wtot[NWARP];
    __shared__ int s_cnt;

    const unsigned* gm = g_mask + (size_t)bm * WORDS;
    const unsigned w0 = gm[tid * 2 + 0];
    const unsigned w1 = gm[tid * 2 + 1];
    const int c0 = __popc(w0);
    const int myc = c0 + __popc(w1);

    int scan = myc;
    #pragma unroll
    for (int d = 1; d < 32; d <<= 1) {
        const int v = __shfl_up_sync(0xffffffffu, scan, d);
        if (lane >= d) scan += v;
    }
    if (lane == 31) s_wtot[w] = scan;
    __syncthreads();
    int wbase = 0, tot = 0;
    #pragma unroll
    for (int j = 0; j < NWARP; ++j) {
        const int c = s_wtot[j];
        if (j < w) wbase += c;
        tot += c;
    }
    const int excl = wbase + scan - myc;

    if (excl < NS && myc) {
        int p = excl;
        unsigned ww = w0;
        while (ww) {
            const int bit = __ffs(ww) - 1;
            ww &= ww - 1;
            if (p < NS) s_idx[p] = tid * 64 + bit;
            ++p;
        }
        p = excl + c0;
        ww = w1;
        while (ww) {
            const int bit = __ffs(ww) - 1;
            ww &= ww - 1;
            if (p < NS) s_idx[p] = tid * 64 + 32 + bit;
            ++p;
        }
    }
    if (tid == 0) s_cnt = tot;
    __syncthreads();

    const int cnt = s_cnt;
    const size_t flag_base = (size_t)NBOX * NS * ROW;
    if (tid == 0) {
        g_cnt[bm] = cnt;
        __stcs(out + flag_base + bm, (cnt == 0) ? 1.0f : 0.0f);
    }
    if (cnt == 0) return;
    for (int k = tid; k < NS; k += BLOCK)
        g_rows[bm * NS + k] = s_idx[(cnt >= NS) ? k : (k % cnt)];
}

// ---------------- Kernel C: pure gather (8 CTAs/box, 4 rows/warp one-shot, streaming stores) ----------------
__global__ __launch_bounds__(BLOCK)
void kC_gather(const float* __restrict__ points,
               const float* __restrict__ feats,
               float* __restrict__ out)
{
    const int part = blockIdx.x & (GPARTS - 1);
    const int bm   = blockIdx.x >> 3;
    const int b    = bm >> 7;
    const int k0   = part * GROWS;
    const int tid  = threadIdx.x;
    const int w    = tid >> 5;
    const int lane = tid & 31;

    const int cnt = g_cnt[bm];
    const size_t obase = (size_t)bm * NS * ROW + (size_t)k0 * ROW;

    if (cnt == 0) {
        float4* o4 = (float4*)(out + obase);
        const float4 z = make_float4(0.f, 0.f, 0.f, 0.f);
        for (int e = tid; e < PARTF / 4; e += BLOCK)
            __stcs(o4 + e, z);
        return;
    }

    __shared__ int s_row[GROWS];
    if (tid < GROWS) s_row[tid] = __ldg(&g_rows[bm * NS + k0 + tid]);
    __syncthreads();

    const float* pts = points + (size_t)b * NN * 3;
    const float* ft  = feats  + (size_t)b * NN * CC;

    // 2 batches of 4 rows per warp; per batch all 20 LDGs issued before stores.
    #pragma unroll
    for (int it = 0; it < GROWS / (4 * NWARP); ++it) {
        const int r0 = 4 * (w + NWARP * it);
        int idx[4];
        #pragma unroll
        for (int i = 0; i < 4; ++i) idx[i] = s_row[r0 + i];

        float v[4][4];
        #pragma unroll
        for (int i = 0; i < 4; ++i) {
            const float* src = ft + (size_t)idx[i] * CC;
            #pragma unroll
            for (int j = 0; j < 4; ++j) v[i][j] = src[lane + 32 * j];
        }
        float pv[4];
        #pragma unroll
        for (int i = 0; i < 4; ++i)
            pv[i] = (lane < 3) ? pts[idx[i] * 3 + lane] : 0.f;

        #pragma unroll
        for (int i = 0; i < 4; ++i) {
            const size_t base = obase + (size_t)(r0 + i) * ROW;
            if (lane < 3) __stcs(out + base + lane, pv[i]);
            float* dst = out + base + 3;
            #pragma unroll
            for (int j = 0; j < 4; ++j) __stcs(dst + lane + 32 * j, v[i][j]);
        }
    }
}

extern "C" void kernel_launch(void* const* d_in, const int* in_sizes, int n_in,
                              void* d_out, int out_size) {
    const float* points = (const float*)d_in[0];   // [4,16384,3]
    const float* feats  = (const float*)d_in[1];   // [4,16384,128]
    const float* boxes  = (const float*)d_in[2];   // [4,128,7]
    float* out = (float*)d_out;
    kA_mask<<<BB * PCHUNKS * ASPLIT, BLOCK>>>(points, boxes);
    kB_scan<<<NBOX, BLOCK>>>(out);
    kC_gather<<<NBOX * GPARTS, BLOCK>>>(points, feats, out);
}